// round 6
// baseline (speedup 1.0000x reference)
#include <cuda_runtime.h>
#include <cuda_bf16.h>

// CapsuleModel2: gather[P,272] -> segment mean (sorted ids) -> sigmoid(linear)
// R6: 4 CTAs/SM (reg cap ~56 => 8 LDG.128 truly in flight), packed f32x2
// accumulation, int4 index staging (contiguous per-plane quarters), 32-bit
// gather addressing. Persistent single-wave grid, warp-parallel bound search.

#define BLOCK   288            // 9 warps; 272 active in gather (68 slots x 4 planes)
#define PLANES  4
#define CHUNK   256
#define MAXSLOT 72             // supports D <= 288
#define NWARP   (BLOCK / 32)
#define MAXSEG  16             // max segments per CTA (+1 boundary)

__device__ __forceinline__ unsigned long long f2add(unsigned long long a,
                                                    unsigned long long b) {
    unsigned long long r;
    asm("add.rn.f32x2 %0, %1, %2;" : "=l"(r) : "l"(a), "l"(b));
    return r;
}
__device__ __forceinline__ unsigned long long d2u(double d) {
    return (unsigned long long)__double_as_longlong(d);
}

__global__ __launch_bounds__(BLOCK, 4)
void capsule_seg_pool_kernel(const double2* __restrict__ feats2,  // [G, D/4] 16B slots
                             const float*   __restrict__ Wm,      // [D, NC]
                             const float*   __restrict__ bias,    // [NC]
                             const int*     __restrict__ point_idx,
                             const int*     __restrict__ segment_ids,
                             float*         __restrict__ out,     // [NI, NC]
                             int P, int D, int NC, int NI, int G)
{
    __shared__ int    s_bound[MAXSEG + 1];
    __shared__ __align__(16) int s_idx[CHUNK];
    __shared__ float4 s_acc[PLANES * MAXSLOT];
    __shared__ float  s_pooled[4 * MAXSLOT];

    const int tid   = threadIdx.x;
    const int lane  = tid & 31;
    const int wid   = tid >> 5;
    const int SLOTS = D >> 2;                  // 68 for D=272
    const unsigned SLOTSu = (unsigned)SLOTS;

    // --- this CTA's contiguous segment block (balanced split) ---
    const int lo_seg = (int)(((long long)blockIdx.x)     * NI / G);
    const int hi_seg = (int)(((long long)blockIdx.x + 1) * NI / G);
    const int nseg   = hi_seg - lo_seg;
    if (nseg <= 0) return;

    // --- boundaries in parallel: warp w does 32-ary lower_bound(lo_seg + w) ---
    for (int t = wid; t <= nseg; t += NWARP) {
        const int target = lo_seg + t;
        int lo = 0, hi = P;
        while (hi - lo > 32) {
            const int step = ((hi - lo) + 31) >> 5;
            int m = lo + lane * step;
            m = min(m, hi - 1);
            const bool lt = (__ldg(&segment_ids[m]) < target);
            const unsigned bal = __ballot_sync(0xffffffffu, lt);
            const int k = __popc(bal);
            int nlo = (k == 0)  ? lo : min(lo + (k - 1) * step + 1, hi);
            int nhi = (k == 32) ? hi : min(lo + k * step, hi);
            lo = nlo; hi = nhi;
        }
        {
            const int m = lo + lane;
            const bool lt = (m < hi) ? (__ldg(&segment_ids[m]) < target) : false;
            lo += __popc(__ballot_sync(0xffffffffu, lt));
        }
        if (lane == 0) s_bound[t] = lo;
    }
    __syncthreads();

    const bool active = (tid < SLOTS * PLANES);
    const int  slot   = active ? (tid % SLOTS) : 0;
    const int  plane  = active ? (tid / SLOTS) : 0;
    const double2* fbase = feats2 + slot;      // row r -> fbase[r * SLOTS]

    for (int s = 0; s < nseg; ++s) {
        const int seg   = lo_seg + s;
        const int start = s_bound[s];
        const int end   = s_bound[s + 1];
        const int count = end - start;

        unsigned long long acc0 = 0ull, acc1 = 0ull;   // packed f32x2 accumulators

        for (int base = start; base < end; base += CHUNK) {
            const int n = min(CHUNK, end - base);
            for (int j = tid; j < n; j += BLOCK)
                s_idx[j] = __ldg(&point_idx[base + j]);
            __syncthreads();

            if (active) {
                // contiguous, 4-aligned quarter per plane
                const int quarter = ((n + 15) >> 4) << 2;
                const int pstart  = min(plane * quarter, n);
                const int pend    = min(pstart + quarter, n);
                int i = pstart;
                for (; i + 8 <= pend; i += 8) {
                    const int4 ia = *(const int4*)&s_idx[i];
                    const int4 ib = *(const int4*)&s_idx[i + 4];
                    double2 v0 = __ldg(fbase + (unsigned)ia.x * SLOTSu);
                    double2 v1 = __ldg(fbase + (unsigned)ia.y * SLOTSu);
                    double2 v2 = __ldg(fbase + (unsigned)ia.z * SLOTSu);
                    double2 v3 = __ldg(fbase + (unsigned)ia.w * SLOTSu);
                    double2 v4 = __ldg(fbase + (unsigned)ib.x * SLOTSu);
                    double2 v5 = __ldg(fbase + (unsigned)ib.y * SLOTSu);
                    double2 v6 = __ldg(fbase + (unsigned)ib.z * SLOTSu);
                    double2 v7 = __ldg(fbase + (unsigned)ib.w * SLOTSu);
                    unsigned long long x01 = f2add(d2u(v0.x), d2u(v1.x));
                    unsigned long long x23 = f2add(d2u(v2.x), d2u(v3.x));
                    unsigned long long x45 = f2add(d2u(v4.x), d2u(v5.x));
                    unsigned long long x67 = f2add(d2u(v6.x), d2u(v7.x));
                    unsigned long long y01 = f2add(d2u(v0.y), d2u(v1.y));
                    unsigned long long y23 = f2add(d2u(v2.y), d2u(v3.y));
                    unsigned long long y45 = f2add(d2u(v4.y), d2u(v5.y));
                    unsigned long long y67 = f2add(d2u(v6.y), d2u(v7.y));
                    acc0 = f2add(acc0, f2add(f2add(x01, x23), f2add(x45, x67)));
                    acc1 = f2add(acc1, f2add(f2add(y01, y23), f2add(y45, y67)));
                }
                for (; i < pend; ++i) {
                    double2 v = __ldg(fbase + (unsigned)s_idx[i] * SLOTSu);
                    acc0 = f2add(acc0, d2u(v.x));
                    acc1 = f2add(acc1, d2u(v.y));
                }
            }
            __syncthreads();
        }

        // --- fold planes, apply mean ---
        if (active) {
            const double a0 = __longlong_as_double((long long)acc0);
            const double a1 = __longlong_as_double((long long)acc1);
            s_acc[plane * SLOTS + slot] =
                make_float4(__uint_as_float((unsigned)__double2loint(a0)),
                            __uint_as_float((unsigned)__double2hiint(a0)),
                            __uint_as_float((unsigned)__double2loint(a1)),
                            __uint_as_float((unsigned)__double2hiint(a1)));
        }
        __syncthreads();

        if (tid < SLOTS) {
            float4 a = s_acc[tid];
            float4 b = s_acc[SLOTS + tid];
            float4 c = s_acc[2 * SLOTS + tid];
            float4 d = s_acc[3 * SLOTS + tid];
            const float inv = 1.0f / (float)max(count, 1);
            s_pooled[4 * tid + 0] = ((a.x + b.x) + (c.x + d.x)) * inv;
            s_pooled[4 * tid + 1] = ((a.y + b.y) + (c.y + d.y)) * inv;
            s_pooled[4 * tid + 2] = ((a.z + b.z) + (c.z + d.z)) * inv;
            s_pooled[4 * tid + 3] = ((a.w + b.w) + (c.w + d.w)) * inv;
        }
        __syncthreads();

        // --- fused linear + sigmoid: warp w -> cols w, w+NWARP, ... ---
        for (int c = wid; c < NC; c += NWARP) {
            float dot = 0.f;
            for (int d = lane; d < D; d += 32)
                dot += s_pooled[d] * __ldg(&Wm[(size_t)d * NC + c]);
            #pragma unroll
            for (int off = 16; off > 0; off >>= 1)
                dot += __shfl_down_sync(0xffffffffu, dot, off);
            if (lane == 0) {
                float x = dot + __ldg(&bias[c]);
                out[(size_t)seg * NC + c] = 1.0f / (1.0f + __expf(-x));
            }
        }
        __syncthreads();
    }
}

extern "C" void kernel_launch(void* const* d_in, const int* in_sizes, int n_in,
                              void* d_out, int out_size)
{
    const double2* feats2      = (const double2*)d_in[0];
    const float*   Wm          = (const float*)  d_in[1];
    const float*   bias        = (const float*)  d_in[2];
    const int*     point_idx   = (const int*)    d_in[3];
    const int*     segment_ids = (const int*)    d_in[4];
    float*         out         = (float*)        d_out;

    const int NC = in_sizes[2];            // 19
    const int D  = in_sizes[1] / NC;       // 272
    const int P  = in_sizes[3];            // 524288
    const int NI = out_size / NC;          // 4096

    int G = 152 * 4;                       // one full wave at 4 CTAs/SM
    if (G > NI) G = NI;
    while ((NI + G - 1) / G > MAXSEG - 1) G *= 2;

    capsule_seg_pool_kernel<<<G, BLOCK>>>(feats2, Wm, bias, point_idx,
                                          segment_ids, out, P, D, NC, NI, G);
}

// round 7
// speedup vs baseline: 1.0189x; 1.0189x over previous
#include <cuda_runtime.h>
#include <cuda_bf16.h>

// CapsuleModel2: gather[P,272] -> segment mean (sorted ids) -> sigmoid(linear)
// R7 = R5 base (5 CTAs/SM, single-wave persistent grid, warp-parallel bound
// search, 8x unrolled LDG.128 gather) + warp-aligned slot mapping (no warp
// ever straddles two gather rows) + packed f32x2 accumulation.

#define BLOCK   288            // 9 warps
#define PLANES  4
#define CHUNK   256
#define MAXSLOT 72             // supports D <= 288
#define NWARP   (BLOCK / 32)
#define MAXSEG  16             // max segments per CTA (+1 boundary)

__device__ __forceinline__ unsigned long long f2add(unsigned long long a,
                                                    unsigned long long b) {
    unsigned long long r;
    asm("add.rn.f32x2 %0, %1, %2;" : "=l"(r) : "l"(a), "l"(b));
    return r;
}
__device__ __forceinline__ unsigned long long d2u(double d) {
    return (unsigned long long)__double_as_longlong(d);
}

__global__ __launch_bounds__(BLOCK, 5)
void capsule_seg_pool_kernel(const double2* __restrict__ feats2,  // [G, D/4] 16B slots
                             const float*   __restrict__ Wm,      // [D, NC]
                             const float*   __restrict__ bias,    // [NC]
                             const int*     __restrict__ point_idx,
                             const int*     __restrict__ segment_ids,
                             float*         __restrict__ out,     // [NI, NC]
                             int P, int D, int NC, int NI, int G)
{
    __shared__ int    s_bound[MAXSEG + 1];
    __shared__ int    s_idx[CHUNK];
    __shared__ float4 s_acc[PLANES * MAXSLOT];
    __shared__ float  s_pooled[4 * MAXSLOT];

    const int tid   = threadIdx.x;
    const int lane  = tid & 31;
    const int wid   = tid >> 5;
    const int SLOTS = D >> 2;                  // 68 for D=272

    // --- this CTA's contiguous segment block (balanced split) ---
    const int lo_seg = (int)(((long long)blockIdx.x)     * NI / G);
    const int hi_seg = (int)(((long long)blockIdx.x + 1) * NI / G);
    const int nseg   = hi_seg - lo_seg;
    if (nseg <= 0) return;

    // --- boundaries in parallel: warp w does 32-ary lower_bound(lo_seg + w) ---
    for (int t = wid; t <= nseg; t += NWARP) {
        const int target = lo_seg + t;
        int lo = 0, hi = P;
        while (hi - lo > 32) {
            const int step = ((hi - lo) + 31) >> 5;
            int m = lo + lane * step;
            m = min(m, hi - 1);
            const bool lt = (__ldg(&segment_ids[m]) < target);
            const unsigned bal = __ballot_sync(0xffffffffu, lt);
            const int k = __popc(bal);
            int nlo = (k == 0)  ? lo : min(lo + (k - 1) * step + 1, hi);
            int nhi = (k == 32) ? hi : min(lo + k * step, hi);
            lo = nlo; hi = nhi;
        }
        {
            const int m = lo + lane;
            const bool lt = (m < hi) ? (__ldg(&segment_ids[m]) < target) : false;
            lo += __popc(__ballot_sync(0xffffffffu, lt));
        }
        if (lane == 0) s_bound[t] = lo;
    }
    __syncthreads();

    // --- warp-aligned (single-row-per-warp) slot mapping ---
    //   FULL = SLOTS/32 warp-groups per plane; warps [0, PLANES*FULL) each cover
    //   one 32-slot span of one plane's row. One extra warp covers the
    //   REM = SLOTS%32 tail slots for all planes (PLANES*REM lanes).
    const int FULL = SLOTS >> 5;               // 2 for D=272
    const int REM  = SLOTS & 31;               // 4
    bool active = false;
    int  plane  = 0, slot = 0;
    if (wid < PLANES * FULL) {
        active = true;
        plane  = wid % PLANES;
        slot   = (wid / PLANES) * 32 + lane;
    } else if (wid == PLANES * FULL && lane < PLANES * REM && REM > 0) {
        active = true;
        plane  = lane / REM;
        slot   = FULL * 32 + (lane % REM);
    }
    const char* fbase = (const char*)feats2 + (size_t)slot * 16;
    const unsigned rowbytes = (unsigned)(SLOTS * 16);

    for (int s = 0; s < nseg; ++s) {
        const int seg   = lo_seg + s;
        const int start = s_bound[s];
        const int end   = s_bound[s + 1];
        const int count = end - start;

        unsigned long long acc0 = 0ull, acc1 = 0ull;   // packed f32x2 accumulators

        for (int base = start; base < end; base += CHUNK) {
            const int n = min(CHUNK, end - base);
            for (int j = tid; j < n; j += BLOCK)
                s_idx[j] = __ldg(&point_idx[base + j]);
            __syncthreads();

            if (active) {
                int i = plane;
                const int nmain = n - 7 * PLANES;
                for (; i < nmain; i += 8 * PLANES) {
                    const unsigned o0 = (unsigned)s_idx[i             ] * rowbytes;
                    const unsigned o1 = (unsigned)s_idx[i +     PLANES] * rowbytes;
                    const unsigned o2 = (unsigned)s_idx[i + 2 * PLANES] * rowbytes;
                    const unsigned o3 = (unsigned)s_idx[i + 3 * PLANES] * rowbytes;
                    const unsigned o4 = (unsigned)s_idx[i + 4 * PLANES] * rowbytes;
                    const unsigned o5 = (unsigned)s_idx[i + 5 * PLANES] * rowbytes;
                    const unsigned o6 = (unsigned)s_idx[i + 6 * PLANES] * rowbytes;
                    const unsigned o7 = (unsigned)s_idx[i + 7 * PLANES] * rowbytes;
                    double2 v0 = __ldg((const double2*)(fbase + o0));
                    double2 v1 = __ldg((const double2*)(fbase + o1));
                    double2 v2 = __ldg((const double2*)(fbase + o2));
                    double2 v3 = __ldg((const double2*)(fbase + o3));
                    double2 v4 = __ldg((const double2*)(fbase + o4));
                    double2 v5 = __ldg((const double2*)(fbase + o5));
                    double2 v6 = __ldg((const double2*)(fbase + o6));
                    double2 v7 = __ldg((const double2*)(fbase + o7));
                    unsigned long long x01 = f2add(d2u(v0.x), d2u(v1.x));
                    unsigned long long x23 = f2add(d2u(v2.x), d2u(v3.x));
                    unsigned long long x45 = f2add(d2u(v4.x), d2u(v5.x));
                    unsigned long long x67 = f2add(d2u(v6.x), d2u(v7.x));
                    unsigned long long y01 = f2add(d2u(v0.y), d2u(v1.y));
                    unsigned long long y23 = f2add(d2u(v2.y), d2u(v3.y));
                    unsigned long long y45 = f2add(d2u(v4.y), d2u(v5.y));
                    unsigned long long y67 = f2add(d2u(v6.y), d2u(v7.y));
                    acc0 = f2add(acc0, f2add(f2add(x01, x23), f2add(x45, x67)));
                    acc1 = f2add(acc1, f2add(f2add(y01, y23), f2add(y45, y67)));
                }
                for (; i < n; i += PLANES) {
                    const unsigned o = (unsigned)s_idx[i] * rowbytes;
                    double2 v = __ldg((const double2*)(fbase + o));
                    acc0 = f2add(acc0, d2u(v.x));
                    acc1 = f2add(acc1, d2u(v.y));
                }
            }
            __syncthreads();
        }

        // --- fold planes, apply mean ---
        if (active) {
            const double a0 = __longlong_as_double((long long)acc0);
            const double a1 = __longlong_as_double((long long)acc1);
            s_acc[plane * SLOTS + slot] =
                make_float4(__uint_as_float((unsigned)__double2loint(a0)),
                            __uint_as_float((unsigned)__double2hiint(a0)),
                            __uint_as_float((unsigned)__double2loint(a1)),
                            __uint_as_float((unsigned)__double2hiint(a1)));
        }
        __syncthreads();

        if (tid < SLOTS) {
            float4 a = s_acc[tid];
            float4 b = s_acc[SLOTS + tid];
            float4 c = s_acc[2 * SLOTS + tid];
            float4 d = s_acc[3 * SLOTS + tid];
            const float inv = 1.0f / (float)max(count, 1);
            s_pooled[4 * tid + 0] = ((a.x + b.x) + (c.x + d.x)) * inv;
            s_pooled[4 * tid + 1] = ((a.y + b.y) + (c.y + d.y)) * inv;
            s_pooled[4 * tid + 2] = ((a.z + b.z) + (c.z + d.z)) * inv;
            s_pooled[4 * tid + 3] = ((a.w + b.w) + (c.w + d.w)) * inv;
        }
        __syncthreads();

        // --- fused linear + sigmoid: warp w -> cols w, w+NWARP, ... ---
        for (int c = wid; c < NC; c += NWARP) {
            float dot = 0.f;
            for (int d = lane; d < D; d += 32)
                dot += s_pooled[d] * __ldg(&Wm[(size_t)d * NC + c]);
            #pragma unroll
            for (int off = 16; off > 0; off >>= 1)
                dot += __shfl_down_sync(0xffffffffu, dot, off);
            if (lane == 0) {
                float x = dot + __ldg(&bias[c]);
                out[(size_t)seg * NC + c] = 1.0f / (1.0f + __expf(-x));
            }
        }
        __syncthreads();
    }
}

extern "C" void kernel_launch(void* const* d_in, const int* in_sizes, int n_in,
                              void* d_out, int out_size)
{
    const double2* feats2      = (const double2*)d_in[0];
    const float*   Wm          = (const float*)  d_in[1];
    const float*   bias        = (const float*)  d_in[2];
    const int*     point_idx   = (const int*)    d_in[3];
    const int*     segment_ids = (const int*)    d_in[4];
    float*         out         = (float*)        d_out;

    const int NC = in_sizes[2];            // 19
    const int D  = in_sizes[1] / NC;       // 272
    const int P  = in_sizes[3];            // 524288
    const int NI = out_size / NC;          // 4096

    int G = 152 * 5;                       // one full wave at 5 CTAs/SM
    if (G > NI) G = NI;
    while ((NI + G - 1) / G > MAXSEG - 1) G *= 2;

    capsule_seg_pool_kernel<<<G, BLOCK>>>(feats2, Wm, bias, point_idx,
                                          segment_ids, out, P, D, NC, NI, G);
}